// round 17
// baseline (speedup 1.0000x reference)
#include <cuda_runtime.h>
#include <cuda_fp16.h>
#include <math.h>
#include <math_constants.h>
#include <cstdint>

#define BB   4
#define SS   2048
#define DM   1024
#define NH   16
#define DH   64
#define DFF  4096
#define MTOK (BB*SS)      // 8192
#define LDX  3072

// ---------------- helpers ----------------
__device__ __forceinline__ uint32_t smem_to_u32(const void* p) {
    uint32_t a;
    asm("{ .reg .u64 t; cvta.to.shared.u64 t, %1; cvt.u32.u64 %0, t; }" : "=r"(a) : "l"(p));
    return a;
}
#define CP_ASYNC16(s, g) asm volatile("cp.async.cg.shared.global [%0], [%1], 16;" :: "r"(s), "l"(g))
#define CP_COMMIT()      asm volatile("cp.async.commit_group;" ::: "memory")
#define CP_WAIT0()       asm volatile("cp.async.wait_group 0;" ::: "memory")
#define LDSM4(rg, addr) \
    asm volatile("ldmatrix.sync.aligned.m8n8.x4.shared.b16 {%0,%1,%2,%3}, [%4];" \
        : "=r"((rg)[0]), "=r"((rg)[1]), "=r"((rg)[2]), "=r"((rg)[3]) : "r"(addr))
#define LDSM4T(rg, addr) \
    asm volatile("ldmatrix.sync.aligned.m8n8.x4.trans.shared.b16 {%0,%1,%2,%3}, [%4];" \
        : "=r"((rg)[0]), "=r"((rg)[1]), "=r"((rg)[2]), "=r"((rg)[3]) : "r"(addr))
#define MMA16816(d, a, b0v, b1v) \
    asm volatile("mma.sync.aligned.m16n8k16.row.col.f32.f16.f16.f32 " \
        "{%0,%1,%2,%3}, {%4,%5,%6,%7}, {%8,%9}, {%0,%1,%2,%3};" \
        : "+f"((d)[0]), "+f"((d)[1]), "+f"((d)[2]), "+f"((d)[3]) \
        : "r"((a)[0]), "r"((a)[1]), "r"((a)[2]), "r"((a)[3]), "r"(b0v), "r"(b1v))

__device__ __forceinline__ float ex2(float x) {
    float r; asm("ex2.approx.f32 %0, %1;" : "=f"(r) : "f"(x)); return r;
}
__device__ __forceinline__ float rcpa(float x) {
    float r; asm("rcp.approx.f32 %0, %1;" : "=f"(r) : "f"(x)); return r;
}
// 2^y on the FMA pipe (magic round + deg-5 Taylor), rel err ~2e-6
__device__ __forceinline__ float fast_exp2(float y) {
    y = fmaxf(fminf(y, 126.f), -126.f);
    float z = __fadd_rn(y, 12582912.f);
    int   n = __float_as_int(z) - 0x4B400000;
    float f = __fadd_rn(y, -__fadd_rn(z, -12582912.f));
    float p = fmaf(f, 0.0013333558f, 0.0096181291f);
    p = fmaf(f, p, 0.0555041087f);
    p = fmaf(f, p, 0.2402265069f);
    p = fmaf(f, p, 0.6931471806f);
    p = fmaf(f, p, 1.0f);
    return __int_as_float(__float_as_int(p) + (n << 23));
}
// pack (p0,p1) -> f16x2 hi + f16x2 lo residual
__device__ __forceinline__ void split_pack2(float p0, float p1, uint32_t& h2, uint32_t& l2) {
    __half2 h = __floats2half2_rn(p0, p1);
    float2 hf = __half22float2(h);
    __half2 l = __floats2half2_rn(__fadd_rn(p0, -hf.x), __fadd_rn(p1, -hf.y));
    h2 = *(uint32_t*)&h;
    l2 = *(uint32_t*)&l;
}

// ---------------- scratch (__device__ globals) ----------------
static __device__ __half g_xn_h[(size_t)MTOK*DM],  g_xn_l[(size_t)MTOK*DM];
static __device__ __half g_qkv_h[(size_t)MTOK*LDX], g_qkv_l[(size_t)MTOK*LDX];
static __device__ __half g_at_h[(size_t)MTOK*DM];
static __device__ float  g_res1[(size_t)MTOK*DM];
static __device__ __half g_hn_h[(size_t)MTOK*DM];
static __device__ __half g_sw_h[(size_t)MTOK*DFF];
static __device__ __half g_wqk_h[2048*1024], g_wqk_l[2048*1024];
static __device__ __half g_vw_h [1024*1024];
static __device__ __half g_ow_h [1024*1024];
static __device__ __half g_w13_h[2*DFF*1024];   // interleaved rows
static __device__ __half g_w2_h [1024*DFF];
static __device__ float g_cs[SS*32], g_sn[SS*32];

__global__ void rope_table_kernel(const int* __restrict__ pos) {
    const int s = blockIdx.x, i = threadIdx.x;   // 2048 x 32
    const float inv = exp2f(-(float)i * (13.287712379549449f / 32.0f));
    const float a = (float)pos[s] * inv;
    float sn, cs;
    sincosf(a, &sn, &cs);
    g_cs[s*32 + i] = cs;
    g_sn[s*32 + i] = sn;
}

// ------------- merged weight prep: one launch for all 7 weight tensors --------
#define Q4 262144          // (1024*1024)/4
#define W4 1048576         // (4096*1024)/4
__global__ void prep_weights_kernel(const float* __restrict__ qw,
                                    const float* __restrict__ kw,
                                    const float* __restrict__ vw,
                                    const float* __restrict__ ow,
                                    const float* __restrict__ w1,
                                    const float* __restrict__ w3,
                                    const float* __restrict__ w2,
                                    __half* __restrict__ wqkh,
                                    __half* __restrict__ wqkl,
                                    __half* __restrict__ vwh,
                                    __half* __restrict__ owh,
                                    __half* __restrict__ w13h,
                                    __half* __restrict__ w2h) {
    const int i = blockIdx.x * blockDim.x + threadIdx.x;
    if (i < 2*Q4) {                        // qw | kw -> hi+lo split
        const int j = (i < Q4) ? i : i - Q4;
        const float4 v = (i < Q4) ? ((const float4*)qw)[j] : ((const float4*)kw)[j];
        uint32_t h0, l0, h1, l1;
        split_pack2(v.x, v.y, h0, l0);
        split_pack2(v.z, v.w, h1, l1);
        const uint32_t base = ((i < Q4) ? 0u : (1024u*1024u/2u)) + 2u*(uint32_t)j;
        ((uint32_t*)wqkh)[base] = h0; ((uint32_t*)wqkh)[base+1] = h1;
        ((uint32_t*)wqkl)[base] = l0; ((uint32_t*)wqkl)[base+1] = l1;
    } else if (i < 4*Q4) {                 // vw | ow -> hi only
        const int j = (i < 3*Q4) ? i - 2*Q4 : i - 3*Q4;
        const float4 v = (i < 3*Q4) ? ((const float4*)vw)[j] : ((const float4*)ow)[j];
        __half* dst = (i < 3*Q4) ? vwh : owh;
        ((__half2*)dst)[2*j]   = __floats2half2_rn(v.x, v.y);
        ((__half2*)dst)[2*j+1] = __floats2half2_rn(v.z, v.w);
    } else if (i < 4*Q4 + 2*W4) {          // w1 | w3 -> interleaved hi
        const int off = (i < 4*Q4 + W4) ? 0 : 1;
        const int j = i - 4*Q4 - off*W4;
        const float4 v = off ? ((const float4*)w3)[j] : ((const float4*)w1)[j];
        const int row = j >> 8, c4 = j & 255;
        const size_t o2 = ((size_t)(2*row + off) * 1024 + c4*4) >> 1;
        ((__half2*)w13h)[o2]   = __floats2half2_rn(v.x, v.y);
        ((__half2*)w13h)[o2+1] = __floats2half2_rn(v.z, v.w);
    } else {                               // w2 -> hi only
        const int j = i - 4*Q4 - 2*W4;
        const float4 v = ((const float4*)w2)[j];
        ((__half2*)w2h)[2*j]   = __floats2half2_rn(v.x, v.y);
        ((__half2*)w2h)[2*j+1] = __floats2half2_rn(v.z, v.w);
    }
}

// ---------------- RMSNorm -> split fp16 (hi+lo) ----------------
__global__ void rmsnorm_split_kernel(const float* __restrict__ x,
                                     const float* __restrict__ g,
                                     __half* __restrict__ yh,
                                     __half* __restrict__ yl) {
    const int row = blockIdx.x;
    const float4* xr = (const float4*)(x + (size_t)row * DM);
    const int t = threadIdx.x;
    float4 xv = xr[t];
    float ss = xv.x*xv.x + xv.y*xv.y + xv.z*xv.z + xv.w*xv.w;
    #pragma unroll
    for (int o = 16; o; o >>= 1) ss += __shfl_xor_sync(0xffffffffu, ss, o);
    __shared__ float sred[8];
    const int warp = t >> 5, lane = t & 31;
    if (lane == 0) sred[warp] = ss;
    __syncthreads();
    if (warp == 0) {
        float v = (lane < 8) ? sred[lane] : 0.f;
        #pragma unroll
        for (int o = 4; o; o >>= 1) v += __shfl_xor_sync(0xffffffffu, v, o);
        if (lane == 0) sred[0] = v;
    }
    __syncthreads();
    const float inv = rsqrtf(sred[0] * (1.0f/(float)DM) + 1e-5f);
    const float4 gv = ((const float4*)g)[t];
    uint32_t h0, l0, h1, l1;
    split_pack2(xv.x*inv*gv.x, xv.y*inv*gv.y, h0, l0);
    split_pack2(xv.z*inv*gv.z, xv.w*inv*gv.w, h1, l1);
    const size_t b2 = (size_t)row * (DM/2) + 2*t;
    ((uint32_t*)yh)[b2]   = h0; ((uint32_t*)yh)[b2+1] = h1;
    ((uint32_t*)yl)[b2]   = l0; ((uint32_t*)yl)[b2+1] = l1;
}

// ---------------- RMSNorm -> fp16 hi only ----------------
__global__ void rmsnorm_h_kernel(const float* __restrict__ x,
                                 const float* __restrict__ g,
                                 __half* __restrict__ yh) {
    const int row = blockIdx.x;
    const float4* xr = (const float4*)(x + (size_t)row * DM);
    const int t = threadIdx.x;
    float4 xv = xr[t];
    float ss = xv.x*xv.x + xv.y*xv.y + xv.z*xv.z + xv.w*xv.w;
    #pragma unroll
    for (int o = 16; o; o >>= 1) ss += __shfl_xor_sync(0xffffffffu, ss, o);
    __shared__ float sred[8];
    const int warp = t >> 5, lane = t & 31;
    if (lane == 0) sred[warp] = ss;
    __syncthreads();
    if (warp == 0) {
        float v = (lane < 8) ? sred[lane] : 0.f;
        #pragma unroll
        for (int o = 4; o; o >>= 1) v += __shfl_xor_sync(0xffffffffu, v, o);
        if (lane == 0) sred[0] = v;
    }
    __syncthreads();
    const float inv = rsqrtf(sred[0] * (1.0f/(float)DM) + 1e-5f);
    const float4 gv = ((const float4*)g)[t];
    const size_t b2 = (size_t)row * (DM/2) + 2*t;
    ((__half2*)yh)[b2]   = __floats2half2_rn(xv.x*inv*gv.x, xv.y*inv*gv.y);
    ((__half2*)yh)[b2+1] = __floats2half2_rn(xv.z*inv*gv.z, xv.w*inv*gv.w);
}

#define ROWB    144
#define QSCALE  0.18033688f      // 0.125 * log2(e)

// ---- QK 3-term GEMM v3: CTA 128x128, 4 warps of 64x64, BK=32, 2 CTAs/SM -----
// ldsm:MMA ratio 6 (was 2): removes the smem-crossbar bound.
#define QROWB 80                 // 32 halfs + 16B pad
#define QAL   (128u*QROWB)       // A-lo offset
#define QBH   (2u*128u*QROWB)    // B-hi
#define QBL   (3u*128u*QROWB)    // B-lo
#define QSTG  (4u*128u*QROWB)    // 40960 per stage
__global__ __launch_bounds__(128, 2)
void gemm_qk_fp16x3(const __half* __restrict__ Ah,
                    const __half* __restrict__ Al,
                    const __half* __restrict__ Bh,
                    const __half* __restrict__ Bl,
                    __half* __restrict__ Ch,
                    __half* __restrict__ Cl,
                    int N, int K, int ldc) {
    extern __shared__ char smem[];
    const uint32_t sbase = smem_to_u32(smem);
    const int tid  = threadIdx.x;
    const int lane = tid & 31;
    const int wid  = tid >> 5;           // 0..3
    const int bm = blockIdx.y * 128;
    const int bn = blockIdx.x * 128;
    const int m0w = (wid & 1) * 64;
    const int n0w = (wid >> 1) * 64;

    float acc[4][8][4];
    #pragma unroll
    for (int i = 0; i < 4; i++)
        #pragma unroll
        for (int j = 0; j < 8; j++)
            #pragma unroll
            for (int q = 0; q < 4; q++) acc[i][j][q] = 0.f;

    const int nch = K >> 5;   // BK=32

    auto load_stage = [&](int s, int c) {
        const int k0 = c << 5;
        const uint32_t st = sbase + (uint32_t)s * QSTG;
        #pragma unroll
        for (int i = 0; i < 4; ++i) {
            const int idx = tid + (i << 7);          // 0..511
            const int row = idx >> 2, cc = idx & 3;  // 4 x 16B per 32-half row
            const uint32_t so = (uint32_t)(row * QROWB + cc * 16);
            const size_t ga = (size_t)(bm + row) * K + k0 + cc * 8;
            const size_t gb = (size_t)(bn + row) * K + k0 + cc * 8;
            CP_ASYNC16(st + so,       (const char*)(Ah + ga));
            CP_ASYNC16(st + QAL + so, (const char*)(Al + ga));
            CP_ASYNC16(st + QBH + so, (const char*)(Bh + gb));
            CP_ASYNC16(st + QBL + so, (const char*)(Bl + gb));
        }
        CP_COMMIT();
    };

    const int g = lane >> 3, r = lane & 7;
    const uint32_t aoff = (uint32_t)((m0w + (g & 1) * 8 + r) * QROWB + ((g >> 1) * 8) * 2);
    const uint32_t boff = QBH + (uint32_t)((n0w + (g >> 1) * 8 + r) * QROWB + ((g & 1) * 8) * 2);

    load_stage(0, 0);

    for (int c = 0; c < nch; ++c) {
        CP_WAIT0();
        __syncthreads();
        if (c + 1 < nch) load_stage((c + 1) & 1, c + 1);

        const uint32_t st = sbase + (uint32_t)(c & 1) * QSTG;
        #pragma unroll
        for (int ks = 0; ks < 2; ++ks) {
            uint32_t AhF[4][4], AlF[4][4], BhF[4][4], BlF[4][4];
            const uint32_t ab = st + aoff + (uint32_t)(ks * 32);
            #pragma unroll
            for (int mi = 0; mi < 4; ++mi) {
                LDSM4(AhF[mi], ab + (uint32_t)(mi * 16 * QROWB));
                LDSM4(AlF[mi], ab + QAL + (uint32_t)(mi * 16 * QROWB));
            }
            const uint32_t bb = st + boff + (uint32_t)(ks * 32);
            #pragma unroll
            for (int nb = 0; nb < 4; ++nb) {
                LDSM4(BhF[nb], bb + (uint32_t)(nb * 16 * QROWB));
                LDSM4(BlF[nb], bb + (QBL - QBH) + (uint32_t)(nb * 16 * QROWB));
            }
            #pragma unroll
            for (int mi = 0; mi < 4; ++mi)
                #pragma unroll
                for (int nb = 0; nb < 4; ++nb)
                    #pragma unroll
                    for (int hf = 0; hf < 2; ++hf) {
                        float* d = acc[mi][nb * 2 + hf];
                        MMA16816(d, AhF[mi], BhF[nb][hf*2], BhF[nb][hf*2+1]);
                        MMA16816(d, AlF[mi], BhF[nb][hf*2], BhF[nb][hf*2+1]);
                        MMA16816(d, AhF[mi], BlF[nb][hf*2], BlF[nb][hf*2+1]);
                    }
        }
    }

    const int erow = lane >> 2;
    const int ecol = (lane & 3) * 2;
    #pragma unroll
    for (int mi = 0; mi < 4; ++mi) {
        #pragma unroll
        for (int nj = 0; nj < 8; ++nj) {
            float* d = acc[mi][nj];
            const int row0 = bm + m0w + mi * 16 + erow;
            const int row1 = row0 + 8;
            const int cg   = bn + n0w + nj * 8 + ecol;
            float a0 = d[0], a1 = d[1], b0 = d[2], b1 = d[3];
            {
                const int i = (cg & 63) >> 1;
                const int s0 = (row0 & (SS-1))*32 + i;
                const int s1 = (row1 & (SS-1))*32 + i;
                const float c0 = g_cs[s0], n0 = g_sn[s0];
                const float c1 = g_cs[s1], n1 = g_sn[s1];
                float t0 = a0*c0 - a1*n0, t1 = a0*n0 + a1*c0;
                a0 = t0; a1 = t1;
                float u0 = b0*c1 - b1*n1, u1 = b0*n1 + b1*c1;
                b0 = u0; b1 = u1;
            }
            if (cg < 1024) {  // Q pre-scale into log2 domain
                a0 *= QSCALE; a1 *= QSCALE; b0 *= QSCALE; b1 *= QSCALE;
            }
            uint32_t h0, l0, h1, l1;
            split_pack2(a0, a1, h0, l0);
            split_pack2(b0, b1, h1, l1);
            const size_t o0 = (size_t)row0 * ldc + cg;
            const size_t o1 = (size_t)row1 * ldc + cg;
            *(uint32_t*)(Ch + o0) = h0;
            *(uint32_t*)(Cl + o0) = l0;
            *(uint32_t*)(Ch + o1) = h1;
            *(uint32_t*)(Cl + o1) = l1;
        }
    }
}

// -------- SMALL 1-term GEMM: CTA 128x128, warp 32x64, 2 CTAs/SM ---------------
// MODE 0: C fp32 (+R). MODE 2: swiglu -> Ch. MODE 3: hi-only -> Ch.
template<int MODE>
__global__ __launch_bounds__(256, 2)
void gemm1_mma_fp16(const __half* __restrict__ Ah,
                    const __half* __restrict__ Bh,
                    const float* __restrict__ R,
                    float* __restrict__ C,
                    __half* __restrict__ Ch,
                    int N, int K, int ldc) {
    constexpr uint32_t B_OFFC = 128u * ROWB;
    constexpr uint32_t STG = 256u * ROWB;          // 36864
    extern __shared__ char smem[];
    const uint32_t sbase = smem_to_u32(smem);
    const int tid  = threadIdx.x;
    const int lane = tid & 31;
    const int wid  = tid >> 5;
    const int bm = blockIdx.y * 128;
    const int bn = blockIdx.x * 128;
    const int m0w = (wid & 3) * 32;
    const int n0w = (wid >> 2) * 64;

    float acc[2][8][4];
    #pragma unroll
    for (int i = 0; i < 2; i++)
        #pragma unroll
        for (int j = 0; j < 8; j++)
            #pragma unroll
            for (int q = 0; q < 4; q++) acc[i][j][q] = 0.f;

    const int nch = K >> 6;

    auto load_stage = [&](int s, int c) {
        const int k0 = c << 6;
        const uint32_t st = sbase + (uint32_t)s * STG;
        #pragma unroll
        for (int i = 0; i < 4; ++i) {
            const int idx = tid + (i << 8);
            const int row = idx >> 3, cc = idx & 7;
            const uint32_t so = (uint32_t)(row * ROWB + cc * 16);
            const size_t ga = (size_t)(bm + row) * K + k0 + cc * 8;
            CP_ASYNC16(st + so, (const char*)(Ah + ga));
        }
        #pragma unroll
        for (int i = 0; i < 4; ++i) {
            const int idx = tid + (i << 8);
            const int row = idx >> 3, cc = idx & 7;
            const uint32_t so = (uint32_t)(row * ROWB + cc * 16);
            const size_t gb = (size_t)(bn + row) * K + k0 + cc * 8;
            CP_ASYNC16(st + B_OFFC + so, (const char*)(Bh + gb));
        }
        CP_COMMIT();
    };

    const int g = lane >> 3, r = lane & 7;
    const uint32_t aoff = (uint32_t)((m0w + (g & 1) * 8 + r) * ROWB + ((g >> 1) * 8) * 2);
    const uint32_t boff = B_OFFC + (uint32_t)((n0w + (g >> 1) * 8 + r) * ROWB + ((g & 1) * 8) * 2);

    load_stage(0, 0);

    for (int c = 0; c < nch; ++c) {
        CP_WAIT0();
        __syncthreads();
        if (c + 1 < nch) load_stage((c + 1) & 1, c + 1);

        const uint32_t st = sbase + (uint32_t)(c & 1) * STG;
        #pragma unroll
        for (int ks = 0; ks < 4; ++ks) {
            uint32_t AhF[2][4];
            const uint32_t ab = st + aoff + (uint32_t)(ks * 32);
            #pragma unroll
            for (int mi = 0; mi < 2; ++mi)
                LDSM4(AhF[mi], ab + (uint32_t)(mi * 16 * ROWB));
            const uint32_t bb = st + boff + (uint32_t)(ks * 32);
            #pragma unroll
            for (int nb = 0; nb < 4; ++nb) {
                uint32_t BhF[4];
                LDSM4(BhF, bb + (uint32_t)(nb * 16 * ROWB));
                #pragma unroll
                for (int mi = 0; mi < 2; ++mi)
                    #pragma unroll
                    for (int hf = 0; hf < 2; ++hf)
                        MMA16816(acc[mi][nb * 2 + hf], AhF[mi], BhF[hf*2], BhF[hf*2+1]);
            }
        }
    }

    const int erow = lane >> 2;
    const int ecol = (lane & 3) * 2;
    #pragma unroll
    for (int mi = 0; mi < 2; ++mi) {
        #pragma unroll
        for (int nj = 0; nj < 8; ++nj) {
            float* d = acc[mi][nj];
            const int row0 = bm + m0w + mi * 16 + erow;
            const int row1 = row0 + 8;
            const int cg   = bn + n0w + nj * 8 + ecol;
            if (MODE == 0) {
                const size_t o0 = (size_t)row0 * ldc + cg;
                const size_t o1 = (size_t)row1 * ldc + cg;
                float2 v0 = make_float2(d[0], d[1]);
                float2 v1 = make_float2(d[2], d[3]);
                if (R) {
                    const float2 r0 = *(const float2*)(R + o0);
                    const float2 r1 = *(const float2*)(R + o1);
                    v0.x += r0.x; v0.y += r0.y;
                    v1.x += r1.x; v1.y += r1.y;
                }
                *(float2*)(C + o0) = v0;
                *(float2*)(C + o1) = v1;
            } else if (MODE == 3) {
                const size_t o0 = (size_t)row0 * ldc + cg;
                const size_t o1 = (size_t)row1 * ldc + cg;
                *(__half2*)(Ch + o0) = __floats2half2_rn(d[0], d[1]);
                *(__half2*)(Ch + o1) = __floats2half2_rn(d[2], d[3]);
            } else {  // MODE 2: swiglu
                const int j = cg >> 1;
                float sl0, sl1;
                if (nj < 3) {
                    const float e0 = ex2(-1.44269504f * d[0]);
                    const float e1 = ex2(-1.44269504f * d[2]);
                    const float dd0 = 1.f + e0, dd1 = 1.f + e1;
                    float r0 = rcpa(dd0); r0 = r0 * (2.f - dd0 * r0);
                    float r1 = rcpa(dd1); r1 = r1 * (2.f - dd1 * r1);
                    sl0 = d[0] * r0 * d[1];
                    sl1 = d[2] * r1 * d[3];
                } else {
                    const float e0 = fast_exp2(-1.44269504f * d[0]);
                    const float e1 = fast_exp2(-1.44269504f * d[2]);
                    const float dd0 = 1.f + e0, dd1 = 1.f + e1;
                    float r0 = __int_as_float(0x7EF311C3 - __float_as_int(dd0));
                    r0 = r0 * (2.f - dd0 * r0); r0 = r0 * (2.f - dd0 * r0);
                    float r1 = __int_as_float(0x7EF311C3 - __float_as_int(dd1));
                    r1 = r1 * (2.f - dd1 * r1); r1 = r1 * (2.f - dd1 * r1);
                    sl0 = d[0] * r0 * d[1];
                    sl1 = d[2] * r1 * d[3];
                }
                Ch[(size_t)row0 * ldc + j] = __float2half_rn(sl0);
                Ch[(size_t)row1 * ldc + j] = __float2half_rn(sl1);
            }
        }
    }
}

// ----- HMMA flash attention (QK 3-term, PV 1-term), R15 known-good ------------
#define ATB (64*144)
#define ATT_SMEM (8*ATB)     // Qh,Ql + 2 stages x (Kh,Kl,Vh) = 73728
__global__ __launch_bounds__(128, 3)
void attn_mma_kernel(const __half* __restrict__ Xh,
                     const __half* __restrict__ Xl,
                     __half* __restrict__ Oh) {
    extern __shared__ char sm[];
    const uint32_t sQh = smem_to_u32(sm);
    const uint32_t sQl = sQh + ATB;
    const uint32_t sSt = sQh + 2*ATB;

    const int tid = threadIdx.x, lane = tid & 31, warp = tid >> 5;
    const int bh = blockIdx.y, b = bh >> 4, h = bh & (NH-1);
    const int qt = gridDim.x - 1 - blockIdx.x;
    const int q0 = qt * 64;
    const size_t rowbase = (size_t)b * SS * LDX;
    const int colQ = h*DH, colK = 1024 + h*DH, colV = 2048 + h*DH;

    #pragma unroll
    for (int i = 0; i < 4; i++) {
        const int idx = tid + i*128;
        const int r = idx >> 3, c = idx & 7;
        const uint32_t so = (uint32_t)(r*144 + c*16);
        const size_t ga = rowbase + (size_t)(q0 + r)*LDX + colQ + c*8;
        CP_ASYNC16(sQh + so, (const char*)(Xh + ga));
        CP_ASYNC16(sQl + so, (const char*)(Xl + ga));
    }
    CP_COMMIT();

    auto load_kv = [&](int t, int s) {
        const int k0 = t * 64;
        #pragma unroll
        for (int i = 0; i < 4; i++) {
            const int idx = tid + i*128;
            const int r = idx >> 3, c = idx & 7;
            const uint32_t so = (uint32_t)s*3*ATB + (uint32_t)(r*144 + c*16);
            const size_t gk = rowbase + (size_t)(k0 + r)*LDX + colK + c*8;
            const size_t gv = rowbase + (size_t)(k0 + r)*LDX + colV + c*8;
            CP_ASYNC16(sSt + so,         (const char*)(Xh + gk));
            CP_ASYNC16(sSt + ATB + so,   (const char*)(Xl + gk));
            CP_ASYNC16(sSt + 2*ATB + so, (const char*)(Xh + gv));
        }
        CP_COMMIT();
    };
    load_kv(0, 0);

    const int g = lane >> 3, rr = lane & 7;
    const uint32_t aoff = (uint32_t)((warp*16 + (g&1)*8 + rr)*144 + (g>>1)*16);
    const uint32_t boff = (uint32_t)(((g>>1)*8 + rr)*144 + (g&1)*16);
    const uint32_t voff = (uint32_t)(((g&1)*8 + rr)*144 + (lane>>4)*16);

    float m0 = -CUDART_INF_F, m1 = -CUDART_INF_F, l0 = 0.f, l1 = 0.f;
    float o[8][4];
    #pragma unroll
    for (int j = 0; j < 8; j++)
        #pragma unroll
        for (int q = 0; q < 4; q++) o[j][q] = 0.f;

    const int r0g = q0 + warp*16 + (lane >> 2);
    const int r1g = r0g + 8;
    const int ntiles = qt + 1;

    for (int t = 0; t < ntiles; t++) {
        CP_WAIT0();
        __syncthreads();
        if (t + 1 < ntiles) load_kv(t + 1, (t + 1) & 1);

        const uint32_t sK  = sSt + (uint32_t)(t & 1)*3*ATB;
        const uint32_t sKl = sK + ATB;
        const uint32_t sV  = sK + 2*ATB;

        float s[8][4];
        #pragma unroll
        for (int j = 0; j < 8; j++)
            #pragma unroll
            for (int q = 0; q < 4; q++) s[j][q] = 0.f;

        #pragma unroll
        for (int d = 0; d < 4; d++) {
            uint32_t qh[4], ql[4];
            LDSM4(qh, sQh + aoff + d*32);
            LDSM4(ql, sQl + aoff + d*32);
            #pragma unroll
            for (int nb = 0; nb < 4; nb++) {
                uint32_t kh[4], kl[4];
                LDSM4(kh, sK  + boff + (uint32_t)(nb*16*144) + d*32);
                LDSM4(kl, sKl + boff + (uint32_t)(nb*16*144) + d*32);
                #pragma unroll
                for (int f = 0; f < 2; f++) {
                    float* dd = s[nb*2 + f];
                    MMA16816(dd, qh, kh[2*f], kh[2*f+1]);
                    MMA16816(dd, qh, kl[2*f], kl[2*f+1]);
                    MMA16816(dd, ql, kh[2*f], kh[2*f+1]);
                }
            }
        }

        const int k0 = t * 64;
        float mx0 = -CUDART_INF_F, mx1 = -CUDART_INF_F;
        #pragma unroll
        for (int j = 0; j < 8; j++) {
            if (t == qt) {
                const int c = k0 + j*8 + (lane & 3)*2;
                if (c     > r0g) s[j][0] = -CUDART_INF_F;
                if (c + 1 > r0g) s[j][1] = -CUDART_INF_F;
                if (c     > r1g) s[j][2] = -CUDART_INF_F;
                if (c + 1 > r1g) s[j][3] = -CUDART_INF_F;
            }
            mx0 = fmaxf(mx0, fmaxf(s[j][0], s[j][1]));
            mx1 = fmaxf(mx1, fmaxf(s[j][2], s[j][3]));
        }
        mx0 = fmaxf(mx0, __shfl_xor_sync(0xffffffffu, mx0, 1));
        mx0 = fmaxf(mx0, __shfl_xor_sync(0xffffffffu, mx0, 2));
        mx1 = fmaxf(mx1, __shfl_xor_sync(0xffffffffu, mx1, 1));
        mx1 = fmaxf(mx1, __shfl_xor_sync(0xffffffffu, mx1, 2));
        const float mn0 = fmaxf(m0, mx0), mn1 = fmaxf(m1, mx1);
        const float cr0 = ex2(m0 - mn0), cr1 = ex2(m1 - mn1);
        m0 = mn0; m1 = mn1;

        float sum0 = 0.f, sum1 = 0.f;
        #pragma unroll
        for (int j = 0; j < 8; j++) {
            if (j < 5) {
                s[j][0] = ex2(s[j][0] - mn0); s[j][1] = ex2(s[j][1] - mn0);
                s[j][2] = ex2(s[j][2] - mn1); s[j][3] = ex2(s[j][3] - mn1);
            } else {
                s[j][0] = fast_exp2(s[j][0] - mn0); s[j][1] = fast_exp2(s[j][1] - mn0);
                s[j][2] = fast_exp2(s[j][2] - mn1); s[j][3] = fast_exp2(s[j][3] - mn1);
            }
            sum0 += s[j][0] + s[j][1];
            sum1 += s[j][2] + s[j][3];
        }
        sum0 += __shfl_xor_sync(0xffffffffu, sum0, 1);
        sum0 += __shfl_xor_sync(0xffffffffu, sum0, 2);
        sum1 += __shfl_xor_sync(0xffffffffu, sum1, 1);
        sum1 += __shfl_xor_sync(0xffffffffu, sum1, 2);
        l0 = l0 * cr0 + sum0;
        l1 = l1 * cr1 + sum1;
        #pragma unroll
        for (int j = 0; j < 8; j++) {
            o[j][0] *= cr0; o[j][1] *= cr0;
            o[j][2] *= cr1; o[j][3] *= cr1;
        }

        #pragma unroll
        for (int kt = 0; kt < 4; kt++) {
            uint32_t ph[4];
            #pragma unroll
            for (int u = 0; u < 4; u++) {
                const int jj = 2*kt + (u >> 1);
                __half2 hh = __floats2half2_rn(s[jj][(u & 1)*2], s[jj][(u & 1)*2 + 1]);
                ph[u] = *(uint32_t*)&hh;
            }
            #pragma unroll
            for (int nb = 0; nb < 4; nb++) {
                uint32_t vh[4];
                const uint32_t va = voff + (uint32_t)(kt*16*144) + (uint32_t)(nb*32);
                LDSM4T(vh, sV + va);
                #pragma unroll
                for (int f = 0; f < 2; f++) {
                    float* dd = o[nb*2 + f];
                    MMA16816(dd, ph, vh[2*f], vh[2*f+1]);
                }
            }
        }
    }

    const float inv0 = 1.0f / l0, inv1 = 1.0f / l1;
    const size_t tok0 = (size_t)b * SS + r0g;
    const size_t tok1 = tok0 + 8;
    #pragma unroll
    for (int j = 0; j < 8; j++) {
        const int col = h*DH + j*8 + (lane & 3)*2;
        __half2 h0 = __floats2half2_rn(o[j][0]*inv0, o[j][1]*inv0);
        __half2 h1 = __floats2half2_rn(o[j][2]*inv1, o[j][3]*inv1);
        *(__half2*)(Oh + tok0*DM + col) = h0;
        *(__half2*)(Oh + tok1*DM + col) = h1;
    }
}

// ---------------- launch ----------------
extern "C" void kernel_launch(void* const* d_in, const int* in_sizes, int n_in,
                              void* d_out, int out_size) {
    const float* x   = (const float*)d_in[0];
    const int*   pos = (const int*)  d_in[1];
    const float* qw  = (const float*)d_in[2];
    const float* kw  = (const float*)d_in[3];
    const float* vw  = (const float*)d_in[4];
    const float* ow  = (const float*)d_in[5];
    const float* g1  = (const float*)d_in[6];
    const float* g2  = (const float*)d_in[7];
    const float* w1  = (const float*)d_in[8];
    const float* w2  = (const float*)d_in[9];
    const float* w3  = (const float*)d_in[10];
    float* out = (float*)d_out;

    __half *xnh, *xnl, *qkvh, *qkvl, *ath, *hnh, *swh;
    __half *wqkh, *wqkl, *vwh, *owh, *w13h, *w2h;
    float *res1;
    cudaGetSymbolAddress((void**)&xnh, g_xn_h);   cudaGetSymbolAddress((void**)&xnl, g_xn_l);
    cudaGetSymbolAddress((void**)&qkvh, g_qkv_h); cudaGetSymbolAddress((void**)&qkvl, g_qkv_l);
    cudaGetSymbolAddress((void**)&ath, g_at_h);
    cudaGetSymbolAddress((void**)&res1, g_res1);
    cudaGetSymbolAddress((void**)&hnh, g_hn_h);
    cudaGetSymbolAddress((void**)&swh, g_sw_h);
    cudaGetSymbolAddress((void**)&wqkh, g_wqk_h); cudaGetSymbolAddress((void**)&wqkl, g_wqk_l);
    cudaGetSymbolAddress((void**)&vwh, g_vw_h);
    cudaGetSymbolAddress((void**)&owh, g_ow_h);
    cudaGetSymbolAddress((void**)&w13h, g_w13_h);
    cudaGetSymbolAddress((void**)&w2h, g_w2_h);

    const int SMQ = 2 * (int)QSTG;                // 81920
    const int SMS = 2 * 256 * ROWB;               // 73728
    cudaFuncSetAttribute((const void*)gemm_qk_fp16x3,      cudaFuncAttributeMaxDynamicSharedMemorySize, SMQ);
    cudaFuncSetAttribute((const void*)gemm1_mma_fp16<0>,   cudaFuncAttributeMaxDynamicSharedMemorySize, SMS);
    cudaFuncSetAttribute((const void*)gemm1_mma_fp16<2>,   cudaFuncAttributeMaxDynamicSharedMemorySize, SMS);
    cudaFuncSetAttribute((const void*)gemm1_mma_fp16<3>,   cudaFuncAttributeMaxDynamicSharedMemorySize, SMS);
    cudaFuncSetAttribute((const void*)attn_mma_kernel,     cudaFuncAttributeMaxDynamicSharedMemorySize, ATT_SMEM);

    // 0: rope table
    rope_table_kernel<<<SS, 32>>>(pos);

    // 1: all weight conversions in one launch
    prep_weights_kernel<<<(4*Q4 + 3*W4)/256, 256>>>(
        qw, kw, vw, ow, w1, w3, w2, wqkh, wqkl, vwh, owh, w13h, w2h);

    // 2: rmsnorm(x) -> split
    rmsnorm_split_kernel<<<MTOK, 256>>>(x, g1, xnh, xnl);

    // 3: QK projection v3 (3-term, warp 64x64, 2 CTA/SM) + rope + Qscale + split
    gemm_qk_fp16x3<<<dim3(2048/128, MTOK/128), 128, SMQ>>>(
        xnh, xnl, wqkh, wqkl, qkvh, qkvl, 2048, DM, LDX);

    // 4: V projection (1-term) hi-only
    gemm1_mma_fp16<3><<<dim3(DM/128, MTOK/128), 256, SMS>>>(
        xnh, vwh, nullptr, nullptr, qkvh + 2048, DM, DM, LDX);

    // 5: HMMA flash attention -> fp16 hi
    attn_mma_kernel<<<dim3(SS/64, BB*NH), 128, ATT_SMEM>>>(qkvh, qkvl, ath);

    // 6: O projection (1-term) + residual(x) -> res1 fp32
    gemm1_mma_fp16<0><<<dim3(DM/128, MTOK/128), 256, SMS>>>(
        ath, owh, x, res1, nullptr, DM, DM, DM);

    // 7: rmsnorm(res1) -> hi only
    rmsnorm_h_kernel<<<MTOK, 256>>>(res1, g2, hnh);

    // 8: fused W1||W3 (1-term, interleaved) + swiglu -> sw hi
    gemm1_mma_fp16<2><<<dim3(2*DFF/128, MTOK/128), 256, SMS>>>(
        hnh, w13h, nullptr, nullptr, swh, 2*DFF, DM, DFF);

    // 9: down projection (1-term) + residual(res1) -> out
    gemm1_mma_fp16<0><<<dim3(DM/128, MTOK/128), 256, SMS>>>(
        swh, w2h, res1, out, nullptr, DM, DFF, DM);
}